// round 1
// baseline (speedup 1.0000x reference)
#include <cuda_runtime.h>
#include <cuda_bf16.h>

#define Nn 100000
#define Ee 1600000
#define Hh 128
#define Gg 64
#define EPSf 1e-5f

#define PITCH 132
#define SCAN_BS 1024
#define NBLK ((Nn + SCAN_BS - 1) / SCAN_BS)   // 98
#define SMEM_GEMM ((128 * PITCH + 128 * 128) * 4)

// ---------------- device scratch (no allocations allowed) ----------------
__device__ int   g_deg[Nn];
__device__ float g_dinv[Nn];
__device__ int   g_off[Nn + 1];
__device__ int   g_cursor[Nn];
__device__ int   g_bsum[SCAN_BS];
__device__ int   g_csr_src[Ee];
__device__ float g_csr_w[Ee];
__device__ float g_h[(size_t)Nn * Hh];
__device__ float g_agg[(size_t)Nn * Hh];
__device__ float g_act[(size_t)Nn * Hh];
__device__ float g_res[(size_t)Nn * Hh];
__device__ float g_bnsum[2 * Hh];
__device__ float g_bnsc[2 * Hh];
__device__ float g_xsum[Gg * Hh];
__device__ float g_cnt[Gg];

// ---------------- zero / degree / dinv ----------------
__global__ void k_zero_pre() {
    int i = blockIdx.x * blockDim.x + threadIdx.x;
    if (i < Nn) { g_deg[i] = 0; g_cursor[i] = 0; }
    if (i < Gg * Hh) g_xsum[i] = 0.0f;
    if (i < Gg) g_cnt[i] = 0.0f;
}

__global__ void k_zero_bn() {
    int i = threadIdx.x;
    if (i < 2 * Hh) g_bnsum[i] = 0.0f;
}

__global__ void k_deg(const int* __restrict__ dst) {
    int e = blockIdx.x * blockDim.x + threadIdx.x;
    if (e < Ee) atomicAdd(&g_deg[dst[e]], 1);
}

__global__ void k_dinv() {
    int i = blockIdx.x * blockDim.x + threadIdx.x;
    if (i < Nn) g_dinv[i] = rsqrtf((float)g_deg[i] + 1.0f);
}

// ---------------- exclusive scan of degrees -> CSR offsets ----------------
__global__ void k_scan1() {
    __shared__ int s[SCAN_BS];
    int tid = threadIdx.x;
    int i = blockIdx.x * SCAN_BS + tid;
    int v = (i < Nn) ? g_deg[i] : 0;
    s[tid] = v;
    __syncthreads();
    for (int d = 1; d < SCAN_BS; d <<= 1) {
        int t = (tid >= d) ? s[tid - d] : 0;
        __syncthreads();
        s[tid] += t;
        __syncthreads();
    }
    if (i < Nn) g_off[i] = s[tid] - v;            // exclusive within block
    if (tid == SCAN_BS - 1) g_bsum[blockIdx.x] = s[tid];
}

__global__ void k_scan2() {
    __shared__ int s[128];
    int tid = threadIdx.x;
    int v = (tid < NBLK) ? g_bsum[tid] : 0;
    s[tid] = v;
    __syncthreads();
    for (int d = 1; d < 128; d <<= 1) {
        int t = (tid >= d) ? s[tid - d] : 0;
        __syncthreads();
        s[tid] += t;
        __syncthreads();
    }
    g_bsum[tid] = s[tid] - v;                      // exclusive block offsets
}

__global__ void k_scan3() {
    int i = blockIdx.x * blockDim.x + threadIdx.x;
    if (i < Nn) g_off[i] += g_bsum[i >> 10];
    if (i == 0) g_off[Nn] = Ee;
}

__global__ void k_fill(const int* __restrict__ src, const int* __restrict__ dst) {
    int e = blockIdx.x * blockDim.x + threadIdx.x;
    if (e >= Ee) return;
    int d = dst[e];
    int s = src[e];
    int pos = g_off[d] + atomicAdd(&g_cursor[d], 1);
    g_csr_src[pos] = s;
    g_csr_w[pos] = g_dinv[s] * g_dinv[d];
}

// ---------------- GEMM: C[M,128] = A[M,128] @ W[128,128], C = g_h ----------------
__global__ __launch_bounds__(256) void gemm_k(const float* __restrict__ Ain,
                                              const float* __restrict__ W, int M) {
    extern __shared__ float sm[];
    float* Xs = sm;                        // [128][PITCH]
    float* Ws = sm + 128 * PITCH;          // [128][128]
    const float* A = Ain ? Ain : g_act;

    int tid = threadIdx.x;
    int row0 = blockIdx.x * 128;

    const float4* W4 = (const float4*)W;
    float4* Ws4 = (float4*)Ws;
#pragma unroll
    for (int i = 0; i < 16; i++) Ws4[tid + i * 256] = W4[tid + i * 256];

#pragma unroll
    for (int i = 0; i < 16; i++) {
        int fid = tid + i * 256;           // 0..4095
        int r = fid >> 5;
        int kq = fid & 31;
        float4 v = make_float4(0.f, 0.f, 0.f, 0.f);
        int gr = row0 + r;
        if (gr < M) v = ((const float4*)A)[(size_t)gr * 32 + kq];
        ((float4*)(Xs + r * PITCH))[kq] = v;
    }
    __syncthreads();

    int tc = tid & 7;      // 8 col groups x 16 cols
    int tr = tid >> 3;     // 32 row groups x 4 rows
    float acc[4][16];
#pragma unroll
    for (int m = 0; m < 4; m++)
#pragma unroll
        for (int j = 0; j < 16; j++) acc[m][j] = 0.0f;

    const float* xb = Xs + (tr * 4) * PITCH;
    const float4* Wsr = (const float4*)Ws;

#pragma unroll 2
    for (int k = 0; k < 128; k++) {
        float xv[4];
#pragma unroll
        for (int m = 0; m < 4; m++) xv[m] = xb[m * PITCH + k];
#pragma unroll
        for (int j = 0; j < 4; j++) {
            float4 w = Wsr[k * 32 + tc * 4 + j];
#pragma unroll
            for (int m = 0; m < 4; m++) {
                acc[m][j * 4 + 0] += xv[m] * w.x;
                acc[m][j * 4 + 1] += xv[m] * w.y;
                acc[m][j * 4 + 2] += xv[m] * w.z;
                acc[m][j * 4 + 3] += xv[m] * w.w;
            }
        }
    }

    int r0 = row0 + tr * 4;
#pragma unroll
    for (int m = 0; m < 4; m++) {
        if (r0 + m < M) {
            float4* cp = (float4*)(g_h + (size_t)(r0 + m) * 128 + tc * 16);
#pragma unroll
            for (int j = 0; j < 4; j++)
                cp[j] = make_float4(acc[m][j * 4 + 0], acc[m][j * 4 + 1],
                                    acc[m][j * 4 + 2], acc[m][j * 4 + 3]);
        }
    }
}

// ---------------- gather: agg = sum_edges h[src]*w + h[i]*dinv^2 + b ----------------
__global__ void k_gather(const float* __restrict__ bias) {
    int wid = (blockIdx.x * blockDim.x + threadIdx.x) >> 5;
    int lane = threadIdx.x & 31;
    if (wid >= Nn) return;

    int beg = g_off[wid];
    int end = g_off[wid + 1];
    float di = g_dinv[wid];
    float d2 = di * di;

    const float4* hv = (const float4*)g_h;
    float4 hs = hv[(size_t)wid * 32 + lane];
    float4 acc = make_float4(hs.x * d2, hs.y * d2, hs.z * d2, hs.w * d2);

    for (int e = beg; e < end; e++) {
        int s = g_csr_src[e];
        float w = g_csr_w[e];
        float4 v = hv[(size_t)s * 32 + lane];
        acc.x += v.x * w;
        acc.y += v.y * w;
        acc.z += v.z * w;
        acc.w += v.w * w;
    }

    float4 b4 = ((const float4*)bias)[lane];
    acc.x += b4.x; acc.y += b4.y; acc.z += b4.z; acc.w += b4.w;
    ((float4*)g_agg)[(size_t)wid * 32 + lane] = acc;
}

// ---------------- batchnorm ----------------
__global__ void k_bnred() {
    int c = threadIdx.x & 127;
    int half = threadIdx.x >> 7;
    float s = 0.f, s2 = 0.f;
    for (int r = blockIdx.x * 2 + half; r < Nn; r += gridDim.x * 2) {
        float v = g_agg[(size_t)r * 128 + c];
        s += v;
        s2 += v * v;
    }
    __shared__ float sh[256];
    sh[threadIdx.x] = s;
    __syncthreads();
    float stot = (half == 0) ? (s + sh[threadIdx.x + 128]) : 0.f;
    __syncthreads();
    sh[threadIdx.x] = s2;
    __syncthreads();
    if (half == 0) {
        float s2tot = s2 + sh[threadIdx.x + 128];
        atomicAdd(&g_bnsum[c], stot);
        atomicAdd(&g_bnsum[128 + c], s2tot);
    }
}

__global__ void k_bnfin(const float* __restrict__ g, const float* __restrict__ be) {
    int c = threadIdx.x;
    float mean = g_bnsum[c] * (1.0f / (float)Nn);
    float var = g_bnsum[128 + c] * (1.0f / (float)Nn) - mean * mean;
    float sc = g[c] * rsqrtf(var + EPSf);
    g_bnsc[c] = sc;
    g_bnsc[128 + c] = be[c] - mean * sc;
}

__global__ void k_apply(int addres) {
    int i = blockIdx.x * blockDim.x + threadIdx.x;
    if (i >= Nn * 32) return;   // N*H/4 float4s
    int c4 = i & 31;
    float4 a = ((const float4*)g_agg)[i];
    float4 sc = ((const float4*)g_bnsc)[c4];
    float4 sh = ((const float4*)g_bnsc)[32 + c4];
    float4 v;
    v.x = fmaxf(fmaf(a.x, sc.x, sh.x), 0.f);
    v.y = fmaxf(fmaf(a.y, sc.y, sh.y), 0.f);
    v.z = fmaxf(fmaf(a.z, sc.z, sh.z), 0.f);
    v.w = fmaxf(fmaf(a.w, sc.w, sh.w), 0.f);
    if (addres) {
        float4 r = ((const float4*)g_res)[i];
        v.x += r.x; v.y += r.y; v.z += r.z; v.w += r.w;
    }
    ((float4*)g_act)[i] = v;
    ((float4*)g_res)[i] = v;
}

// ---------------- pooling (batch is sorted) ----------------
#define PCHUNK 512
__global__ void k_pool(const int* __restrict__ batch) {
    int c = threadIdx.x;
    int start = blockIdx.x * PCHUNK;
    if (start >= Nn) return;
    int end = min(start + PCHUNK, Nn);
    float acc = 0.f, ccnt = 0.f;
    int gp = batch[start];
    for (int n = start; n < end; n++) {
        int g = batch[n];
        if (g != gp) {
            atomicAdd(&g_xsum[gp * 128 + c], acc);
            if (c == 0) atomicAdd(&g_cnt[gp], ccnt);
            acc = 0.f; ccnt = 0.f; gp = g;
        }
        acc += g_act[(size_t)n * 128 + c];
        ccnt += 1.f;
    }
    atomicAdd(&g_xsum[gp * 128 + c], acc);
    if (c == 0) atomicAdd(&g_cnt[gp], ccnt);
}

// ---------------- MLP head ----------------
__global__ void k_mlp(const float* __restrict__ Wm1, const float* __restrict__ bm1,
                      const float* __restrict__ Wm2, const float* __restrict__ bm2,
                      float* __restrict__ out) {
    __shared__ float zs[128], zm[128], hid[128];
    int g = blockIdx.x, c = threadIdx.x;
    float cnt = fmaxf(g_cnt[g], 1.0f);
    float xs = g_xsum[g * 128 + c];
    zs[c] = xs;
    zm[c] = xs / cnt;
    __syncthreads();
    float acc = bm1[c];
#pragma unroll 8
    for (int k = 0; k < 128; k++)
        acc += zs[k] * Wm1[k * 128 + c] + zm[k] * Wm1[(128 + k) * 128 + c];
    hid[c] = fmaxf(acc, 0.f) * Wm2[c];
    __syncthreads();
    for (int s = 64; s > 0; s >>= 1) {
        if (c < s) hid[c] += hid[c + s];
        __syncthreads();
    }
    if (c == 0) out[g] = hid[0] + bm2[0];
}

// ---------------- host ----------------
extern "C" void kernel_launch(void* const* d_in, const int* in_sizes, int n_in,
                              void* d_out, int out_size) {
    const float *x, *W1, *b1, *W2, *b2, *W3, *b3;
    const float *g1, *be1, *g2, *be2, *g3, *be3;
    const float *Wm1, *bm1, *Wm2, *bm2;
    const int *ei, *batch;

    if (in_sizes[1] == 2 * Ee) {
        // setup_inputs dict order
        x   = (const float*)d_in[0];
        ei  = (const int*)  d_in[1];
        batch = (const int*)d_in[2];
        W1 = (const float*)d_in[3];  b1 = (const float*)d_in[4];
        W2 = (const float*)d_in[5];  b2 = (const float*)d_in[6];
        W3 = (const float*)d_in[7];  b3 = (const float*)d_in[8];
        g1 = (const float*)d_in[9];  be1 = (const float*)d_in[10];
        g2 = (const float*)d_in[11]; be2 = (const float*)d_in[12];
        g3 = (const float*)d_in[13]; be3 = (const float*)d_in[14];
        Wm1 = (const float*)d_in[15]; bm1 = (const float*)d_in[16];
        Wm2 = (const float*)d_in[17]; bm2 = (const float*)d_in[18];
    } else {
        // reference signature order
        x   = (const float*)d_in[0];
        W1 = (const float*)d_in[1];  b1 = (const float*)d_in[2];
        g1 = (const float*)d_in[3];  be1 = (const float*)d_in[4];
        W2 = (const float*)d_in[5];  b2 = (const float*)d_in[6];
        g2 = (const float*)d_in[7];  be2 = (const float*)d_in[8];
        W3 = (const float*)d_in[9];  b3 = (const float*)d_in[10];
        g3 = (const float*)d_in[11]; be3 = (const float*)d_in[12];
        Wm1 = (const float*)d_in[13]; bm1 = (const float*)d_in[14];
        Wm2 = (const float*)d_in[15]; bm2 = (const float*)d_in[16];
        ei  = (const int*)d_in[17];
        batch = (const int*)d_in[18];
    }

    const int* src = ei;
    const int* dst = ei + Ee;
    float* out = (float*)d_out;

    cudaFuncSetAttribute(gemm_k, cudaFuncAttributeMaxDynamicSharedMemorySize, SMEM_GEMM);

    const int ZB = (Nn + 255) / 256;          // 391
    const int EB = (Ee + 255) / 256;          // 6250
    const int GEMMB = (Nn + 127) / 128;       // 782
    const int GATB = (Nn * 32 + 255) / 256;   // 12500
    const int POOLB = (Nn + PCHUNK - 1) / PCHUNK;

    k_zero_pre<<<ZB, 256>>>();
    k_deg<<<EB, 256>>>(dst);
    k_dinv<<<ZB, 256>>>();
    k_scan1<<<NBLK, SCAN_BS>>>();
    k_scan2<<<1, 128>>>();
    k_scan3<<<ZB, 256>>>();
    k_fill<<<EB, 256>>>(src, dst);

    // layer 1
    gemm_k<<<GEMMB, 256, SMEM_GEMM>>>(x, W1, Nn);
    k_gather<<<GATB, 256>>>(b1);
    k_zero_bn<<<1, 256>>>();
    k_bnred<<<512, 256>>>();
    k_bnfin<<<1, 128>>>(g1, be1);
    k_apply<<<GATB, 256>>>(0);

    // layer 2
    gemm_k<<<GEMMB, 256, SMEM_GEMM>>>(nullptr, W2, Nn);
    k_gather<<<GATB, 256>>>(b2);
    k_zero_bn<<<1, 256>>>();
    k_bnred<<<512, 256>>>();
    k_bnfin<<<1, 128>>>(g2, be2);
    k_apply<<<GATB, 256>>>(1);

    // layer 3
    gemm_k<<<GEMMB, 256, SMEM_GEMM>>>(nullptr, W3, Nn);
    k_gather<<<GATB, 256>>>(b3);
    k_zero_bn<<<1, 256>>>();
    k_bnred<<<512, 256>>>();
    k_bnfin<<<1, 128>>>(g3, be3);
    k_apply<<<GATB, 256>>>(1);

    // pooling + MLP
    k_pool<<<POOLB, 128>>>(batch);
    k_mlp<<<Gg, 128>>>(Wm1, bm1, Wm2, bm2, out);
}

// round 3
// speedup vs baseline: 1.0976x; 1.0976x over previous
#include <cuda_runtime.h>
#include <cuda_bf16.h>

#define Nn 100000
#define Ee 1600000
#define Hh 128
#define Gg 64
#define EPSf 1e-5f

#define PITCH 132
#define SCAN_BS 1024
#define NBLK ((Nn + SCAN_BS - 1) / SCAN_BS)   // 98
#define SMEM_GEMM ((128 * PITCH + 128 * 128) * 4)

#define FFMA2(d, a, b) asm("fma.rn.f32x2 %0, %1, %2, %0;" : "+l"(d) : "l"(a), "l"(b))

// ---------------- device scratch (no allocations allowed) ----------------
__device__ int   g_deg[Nn];
__device__ float g_dinv[Nn];
__device__ int   g_off[Nn + 1];
__device__ int   g_cursor[Nn];
__device__ int   g_bsum[SCAN_BS];
__device__ int2  g_csr[Ee];               // {src, weight-as-int}
__device__ float g_h[(size_t)Nn * Hh];
__device__ float g_agg[(size_t)Nn * Hh];
__device__ float g_act[(size_t)Nn * Hh];
__device__ float g_bnsum[2 * Hh];
__device__ float g_bnsc[2 * Hh];
__device__ float g_xsum[Gg * Hh];
__device__ float g_cnt[Gg];

// ---------------- zero / degree / dinv ----------------
__global__ void k_zero_pre() {
    int i = blockIdx.x * blockDim.x + threadIdx.x;
    if (i < Nn) { g_deg[i] = 0; g_cursor[i] = 0; }
    if (i < Gg * Hh) g_xsum[i] = 0.0f;
    if (i < Gg) g_cnt[i] = 0.0f;
}

__global__ void k_zero_bn() {
    int i = threadIdx.x;
    if (i < 2 * Hh) g_bnsum[i] = 0.0f;
}

__global__ void k_deg(const int* __restrict__ dst) {
    int e = blockIdx.x * blockDim.x + threadIdx.x;
    if (e < Ee) atomicAdd(&g_deg[dst[e]], 1);
}

__global__ void k_dinv() {
    int i = blockIdx.x * blockDim.x + threadIdx.x;
    if (i < Nn) g_dinv[i] = rsqrtf((float)g_deg[i] + 1.0f);
}

// ---------------- exclusive scan of degrees -> CSR offsets ----------------
__global__ void k_scan1() {
    __shared__ int s[SCAN_BS];
    int tid = threadIdx.x;
    int i = blockIdx.x * SCAN_BS + tid;
    int v = (i < Nn) ? g_deg[i] : 0;
    s[tid] = v;
    __syncthreads();
    for (int d = 1; d < SCAN_BS; d <<= 1) {
        int t = (tid >= d) ? s[tid - d] : 0;
        __syncthreads();
        s[tid] += t;
        __syncthreads();
    }
    if (i < Nn) g_off[i] = s[tid] - v;
    if (tid == SCAN_BS - 1) g_bsum[blockIdx.x] = s[tid];
}

__global__ void k_scan2() {
    __shared__ int s[128];
    int tid = threadIdx.x;
    int v = (tid < NBLK) ? g_bsum[tid] : 0;
    s[tid] = v;
    __syncthreads();
    for (int d = 1; d < 128; d <<= 1) {
        int t = (tid >= d) ? s[tid - d] : 0;
        __syncthreads();
        s[tid] += t;
        __syncthreads();
    }
    g_bsum[tid] = s[tid] - v;
}

__global__ void k_scan3() {
    int i = blockIdx.x * blockDim.x + threadIdx.x;
    if (i < Nn) g_off[i] += g_bsum[i >> 10];
    if (i == 0) g_off[Nn] = Ee;
}

__global__ void k_fill(const int* __restrict__ src, const int* __restrict__ dst) {
    int e = blockIdx.x * blockDim.x + threadIdx.x;
    if (e >= Ee) return;
    int d = dst[e];
    int s = src[e];
    int pos = g_off[d] + atomicAdd(&g_cursor[d], 1);
    g_csr[pos] = make_int2(s, __float_as_int(g_dinv[s] * g_dinv[d]));
}

// ---------------- GEMM: g_h[M,128] = A[M,128] @ W[128,128]  (FFMA2) ----------------
__global__ __launch_bounds__(256) void gemm_k(const float* __restrict__ Ain,
                                              const float* __restrict__ W, int M) {
    extern __shared__ float sm[];
    float* Xs = sm;                        // [128][PITCH]
    float* Ws = sm + 128 * PITCH;          // [128][128]
    const float* A = Ain ? Ain : g_act;

    int tid = threadIdx.x;
    int row0 = blockIdx.x * 128;

    const float4* W4 = (const float4*)W;
    float4* Ws4 = (float4*)Ws;
#pragma unroll
    for (int i = 0; i < 16; i++) Ws4[tid + i * 256] = W4[tid + i * 256];

#pragma unroll
    for (int i = 0; i < 16; i++) {
        int fid = tid + i * 256;
        int r = fid >> 5;
        int kq = fid & 31;
        float4 v = make_float4(0.f, 0.f, 0.f, 0.f);
        int gr = row0 + r;
        if (gr < M) v = ((const float4*)A)[(size_t)gr * 32 + kq];
        ((float4*)(Xs + r * PITCH))[kq] = v;
    }
    __syncthreads();

    int tc = tid & 7;      // 8 col groups x 16 cols
    int tr = tid >> 3;     // 32 row groups x 4 rows

    unsigned long long acc2[4][8];
#pragma unroll
    for (int m = 0; m < 4; m++)
#pragma unroll
        for (int j = 0; j < 8; j++) acc2[m][j] = 0ull;

    const float* xb = Xs + (tr * 4) * PITCH;
    const ulonglong2* Wsr = (const ulonglong2*)Ws;   // 32 ull2 (16B) per 128-float row

#pragma unroll 2
    for (int k = 0; k < 128; k++) {
        unsigned long long xp[4];
#pragma unroll
        for (int m = 0; m < 4; m++) {
            unsigned int xu = __float_as_uint(xb[m * PITCH + k]);
            asm("mov.b64 %0, {%1, %1};" : "=l"(xp[m]) : "r"(xu));
        }
#pragma unroll
        for (int j = 0; j < 4; j++) {
            ulonglong2 w2 = Wsr[k * 32 + tc * 4 + j];   // FIXED: 32 per row (was 16)
#pragma unroll
            for (int m = 0; m < 4; m++) {
                FFMA2(acc2[m][2 * j],     xp[m], w2.x);
                FFMA2(acc2[m][2 * j + 1], xp[m], w2.y);
            }
        }
    }

    int r0 = row0 + tr * 4;
#pragma unroll
    for (int m = 0; m < 4; m++) {
        if (r0 + m < M) {
            ulonglong2* cp = (ulonglong2*)(g_h + (size_t)(r0 + m) * 128 + tc * 16);
#pragma unroll
            for (int j = 0; j < 4; j++)
                cp[j] = make_ulonglong2(acc2[m][2 * j], acc2[m][2 * j + 1]);
        }
    }
}

// ------- gather + bias + fused BN partial stats (block reduce + global atomics) -------
// 512 threads = 16 warps = 16 nodes per block; grid covers exactly Nn nodes.
__global__ __launch_bounds__(512) void k_gather(const float* __restrict__ bias) {
    __shared__ float ss[16 * 128];
    __shared__ float sq[16 * 128];

    int tid = threadIdx.x;
    int wloc = tid >> 5;
    int lane = tid & 31;
    int wid = blockIdx.x * 16 + wloc;   // node id, always < Nn (grid exact)

    int beg = g_off[wid];
    int end = g_off[wid + 1];
    float di = g_dinv[wid];
    float d2 = di * di;

    const float4* hv = (const float4*)g_h;
    float4 hs = hv[(size_t)wid * 32 + lane];
    float4 acc = make_float4(hs.x * d2, hs.y * d2, hs.z * d2, hs.w * d2);

    const int2* csr = g_csr;
    for (int e = beg; e < end; e++) {
        int2 c = csr[e];
        float w = __int_as_float(c.y);
        float4 v = hv[(size_t)c.x * 32 + lane];
        acc.x = fmaf(v.x, w, acc.x);
        acc.y = fmaf(v.y, w, acc.y);
        acc.z = fmaf(v.z, w, acc.z);
        acc.w = fmaf(v.w, w, acc.w);
    }

    float4 b4 = ((const float4*)bias)[lane];
    acc.x += b4.x; acc.y += b4.y; acc.z += b4.z; acc.w += b4.w;
    ((float4*)g_agg)[(size_t)wid * 32 + lane] = acc;

    // stash per-node channel values for BN stats
    int base = wloc * 128 + lane * 4;
    ss[base + 0] = acc.x; ss[base + 1] = acc.y; ss[base + 2] = acc.z; ss[base + 3] = acc.w;
    sq[base + 0] = acc.x * acc.x; sq[base + 1] = acc.y * acc.y;
    sq[base + 2] = acc.z * acc.z; sq[base + 3] = acc.w * acc.w;
    __syncthreads();

    if (tid < 128) {
        float s = 0.f, q = 0.f;
#pragma unroll
        for (int w = 0; w < 16; w++) {
            s += ss[w * 128 + tid];
            q += sq[w * 128 + tid];
        }
        atomicAdd(&g_bnsum[tid], s);
        atomicAdd(&g_bnsum[128 + tid], q);
    }
}

// ---------------- batchnorm finalize + apply ----------------
__global__ void k_bnfin(const float* __restrict__ g, const float* __restrict__ be) {
    int c = threadIdx.x;
    float mean = g_bnsum[c] * (1.0f / (float)Nn);
    float var = g_bnsum[128 + c] * (1.0f / (float)Nn) - mean * mean;
    float sc = g[c] * rsqrtf(var + EPSf);
    g_bnsc[c] = sc;
    g_bnsc[128 + c] = be[c] - mean * sc;
}

__global__ void k_apply(int addres) {
    int i = blockIdx.x * blockDim.x + threadIdx.x;
    if (i >= Nn * 32) return;   // N*H/4 float4s
    int c4 = i & 31;
    float4 a = ((const float4*)g_agg)[i];
    float4 sc = ((const float4*)g_bnsc)[c4];
    float4 sh = ((const float4*)g_bnsc)[32 + c4];
    float4 v;
    v.x = fmaxf(fmaf(a.x, sc.x, sh.x), 0.f);
    v.y = fmaxf(fmaf(a.y, sc.y, sh.y), 0.f);
    v.z = fmaxf(fmaf(a.z, sc.z, sh.z), 0.f);
    v.w = fmaxf(fmaf(a.w, sc.w, sh.w), 0.f);
    if (addres) {
        float4 r = ((const float4*)g_act)[i];   // previous activation = residual
        v.x += r.x; v.y += r.y; v.z += r.z; v.w += r.w;
    }
    ((float4*)g_act)[i] = v;
}

// ---------------- pooling (batch is sorted) ----------------
#define PCHUNK 512
__global__ void k_pool(const int* __restrict__ batch) {
    int c = threadIdx.x;
    int start = blockIdx.x * PCHUNK;
    if (start >= Nn) return;
    int end = min(start + PCHUNK, Nn);
    float acc = 0.f, ccnt = 0.f;
    int gp = batch[start];
    for (int n = start; n < end; n++) {
        int g = batch[n];
        if (g != gp) {
            atomicAdd(&g_xsum[gp * 128 + c], acc);
            if (c == 0) atomicAdd(&g_cnt[gp], ccnt);
            acc = 0.f; ccnt = 0.f; gp = g;
        }
        acc += g_act[(size_t)n * 128 + c];
        ccnt += 1.f;
    }
    atomicAdd(&g_xsum[gp * 128 + c], acc);
    if (c == 0) atomicAdd(&g_cnt[gp], ccnt);
}

// ---------------- MLP head ----------------
__global__ void k_mlp(const float* __restrict__ Wm1, const float* __restrict__ bm1,
                      const float* __restrict__ Wm2, const float* __restrict__ bm2,
                      float* __restrict__ out) {
    __shared__ float zs[128], zm[128], hid[128];
    int g = blockIdx.x, c = threadIdx.x;
    float cnt = fmaxf(g_cnt[g], 1.0f);
    float xs = g_xsum[g * 128 + c];
    zs[c] = xs;
    zm[c] = xs / cnt;
    __syncthreads();
    float acc = bm1[c];
#pragma unroll 8
    for (int k = 0; k < 128; k++)
        acc += zs[k] * Wm1[k * 128 + c] + zm[k] * Wm1[(128 + k) * 128 + c];
    hid[c] = fmaxf(acc, 0.f) * Wm2[c];
    __syncthreads();
    for (int s = 64; s > 0; s >>= 1) {
        if (c < s) hid[c] += hid[c + s];
        __syncthreads();
    }
    if (c == 0) out[g] = hid[0] + bm2[0];
}

// ---------------- host ----------------
extern "C" void kernel_launch(void* const* d_in, const int* in_sizes, int n_in,
                              void* d_out, int out_size) {
    const float *x, *W1, *b1, *W2, *b2, *W3, *b3;
    const float *g1, *be1, *g2, *be2, *g3, *be3;
    const float *Wm1, *bm1, *Wm2, *bm2;
    const int *ei, *batch;

    if (in_sizes[1] == 2 * Ee) {
        x   = (const float*)d_in[0];
        ei  = (const int*)  d_in[1];
        batch = (const int*)d_in[2];
        W1 = (const float*)d_in[3];  b1 = (const float*)d_in[4];
        W2 = (const float*)d_in[5];  b2 = (const float*)d_in[6];
        W3 = (const float*)d_in[7];  b3 = (const float*)d_in[8];
        g1 = (const float*)d_in[9];  be1 = (const float*)d_in[10];
        g2 = (const float*)d_in[11]; be2 = (const float*)d_in[12];
        g3 = (const float*)d_in[13]; be3 = (const float*)d_in[14];
        Wm1 = (const float*)d_in[15]; bm1 = (const float*)d_in[16];
        Wm2 = (const float*)d_in[17]; bm2 = (const float*)d_in[18];
    } else {
        x   = (const float*)d_in[0];
        W1 = (const float*)d_in[1];  b1 = (const float*)d_in[2];
        g1 = (const float*)d_in[3];  be1 = (const float*)d_in[4];
        W2 = (const float*)d_in[5];  b2 = (const float*)d_in[6];
        g2 = (const float*)d_in[7];  be2 = (const float*)d_in[8];
        W3 = (const float*)d_in[9];  b3 = (const float*)d_in[10];
        g3 = (const float*)d_in[11]; be3 = (const float*)d_in[12];
        Wm1 = (const float*)d_in[13]; bm1 = (const float*)d_in[14];
        Wm2 = (const float*)d_in[15]; bm2 = (const float*)d_in[16];
        ei  = (const int*)d_in[17];
        batch = (const int*)d_in[18];
    }

    const int* src = ei;
    const int* dst = ei + Ee;
    float* out = (float*)d_out;

    cudaFuncSetAttribute(gemm_k, cudaFuncAttributeMaxDynamicSharedMemorySize, SMEM_GEMM);

    const int ZB = (Nn + 255) / 256;          // 391
    const int EB = (Ee + 255) / 256;          // 6250
    const int GEMMB = (Nn + 127) / 128;       // 782
    const int GATB = (Nn + 15) / 16;          // 6250 blocks x 512 threads
    const int APPB = (Nn * 32 + 255) / 256;   // 12500
    const int POOLB = (Nn + PCHUNK - 1) / PCHUNK;

    k_zero_pre<<<ZB, 256>>>();
    k_deg<<<EB, 256>>>(dst);
    k_dinv<<<ZB, 256>>>();
    k_scan1<<<NBLK, SCAN_BS>>>();
    k_scan2<<<1, 128>>>();
    k_scan3<<<ZB, 256>>>();
    k_fill<<<EB, 256>>>(src, dst);

    // layer 1
    gemm_k<<<GEMMB, 256, SMEM_GEMM>>>(x, W1, Nn);
    k_zero_bn<<<1, 256>>>();
    k_gather<<<GATB, 512>>>(b1);
    k_bnfin<<<1, 128>>>(g1, be1);
    k_apply<<<APPB, 256>>>(0);

    // layer 2
    gemm_k<<<GEMMB, 256, SMEM_GEMM>>>(nullptr, W2, Nn);
    k_zero_bn<<<1, 256>>>();
    k_gather<<<GATB, 512>>>(b2);
    k_bnfin<<<1, 128>>>(g2, be2);
    k_apply<<<APPB, 256>>>(1);

    // layer 3
    gemm_k<<<GEMMB, 256, SMEM_GEMM>>>(nullptr, W3, Nn);
    k_zero_bn<<<1, 256>>>();
    k_gather<<<GATB, 512>>>(b3);
    k_bnfin<<<1, 128>>>(g3, be3);
    k_apply<<<APPB, 256>>>(1);

    // pooling + MLP
    k_pool<<<POOLB, 128>>>(batch);
    k_mlp<<<Gg, 128>>>(Wm1, bm1, Wm2, bm2, out);
}